// round 9
// baseline (speedup 1.0000x reference)
#include <cuda_runtime.h>
#include <cuda_bf16.h>

#define EPS 0.01f
#define MAX_BLOCKS 8192

__device__ float g_partials[MAX_BLOCKS];   // fully rewritten every run

__global__ void __launch_bounds__(256, 4)   // 64-reg budget: 12 LDG.128 live
elc_main_kernel(const float4* __restrict__ pred4,
                const int4*   __restrict__ label4,
                const float*  __restrict__ Wl,
                const float4* __restrict__ em4,
                int n4)
{
    __shared__ float sWl[16];
    if (threadIdx.x < 16) sWl[threadIdx.x] = Wl[threadIdx.x];
    __syncthreads();

    float acc = 0.0f;
    const int nthreads = gridDim.x * blockDim.x;
    const int gid      = blockIdx.x * blockDim.x + threadIdx.x;
    const int nquads   = n4 >> 2;   // n4 divisible by 4 (8.39M float4s)

    // Each thread consumes 4 CONSECUTIVE float4s per stream, all loads
    // issued back-to-back: a warp presents 2KB contiguous per stream
    // before switching streams -> long DRAM row-hit runs.
    for (int g = gid; g < nquads; g += nthreads) {
        const int i = g << 2;               // first float4 index of the quad
        float4 p0 = pred4[i];
        float4 p1 = pred4[i + 1];
        float4 p2 = pred4[i + 2];
        float4 p3 = pred4[i + 3];
        int4   l0 = label4[i];
        int4   l1 = label4[i + 1];
        int4   l2 = label4[i + 2];
        int4   l3 = label4[i + 3];
        float4 e0 = em4[i];
        float4 e1 = em4[i + 1];
        float4 e2 = em4[i + 2];
        float4 e3 = em4[i + 3];

        // quad 4g..4g+3 shares one channel: c = (16g >> 18) & 15 = (g>>14)&15
        const float w = sWl[(g >> 14) & 15];

        float t = 0.0f;
        if (l0.x == 1) t += __logf(p0.x + EPS) * e0.x;
        if (l0.y == 1) t += __logf(p0.y + EPS) * e0.y;
        if (l0.z == 1) t += __logf(p0.z + EPS) * e0.z;
        if (l0.w == 1) t += __logf(p0.w + EPS) * e0.w;
        if (l1.x == 1) t += __logf(p1.x + EPS) * e1.x;
        if (l1.y == 1) t += __logf(p1.y + EPS) * e1.y;
        if (l1.z == 1) t += __logf(p1.z + EPS) * e1.z;
        if (l1.w == 1) t += __logf(p1.w + EPS) * e1.w;
        if (l2.x == 1) t += __logf(p2.x + EPS) * e2.x;
        if (l2.y == 1) t += __logf(p2.y + EPS) * e2.y;
        if (l2.z == 1) t += __logf(p2.z + EPS) * e2.z;
        if (l2.w == 1) t += __logf(p2.w + EPS) * e2.w;
        if (l3.x == 1) t += __logf(p3.x + EPS) * e3.x;
        if (l3.y == 1) t += __logf(p3.y + EPS) * e3.y;
        if (l3.z == 1) t += __logf(p3.z + EPS) * e3.z;
        if (l3.w == 1) t += __logf(p3.w + EPS) * e3.w;
        acc = fmaf(-w, t, acc);
    }

    // block reduce -> one plain store per block (kernel boundary orders it)
    #pragma unroll
    for (int o = 16; o > 0; o >>= 1)
        acc += __shfl_xor_sync(0xffffffff, acc, o);

    __shared__ float red[8];
    const int lane = threadIdx.x & 31;
    const int wid  = threadIdx.x >> 5;
    if (lane == 0) red[wid] = acc;
    __syncthreads();
    if (wid == 0) {
        acc = (lane < (blockDim.x >> 5)) ? red[lane] : 0.0f;
        #pragma unroll
        for (int o = 4; o > 0; o >>= 1)
            acc += __shfl_xor_sync(0xffffffff, acc, o);
        if (lane == 0) g_partials[blockIdx.x] = acc;
    }
}

__global__ void __launch_bounds__(256)
elc_finalize_kernel(const float* __restrict__ label_sum,
                    int n_blocks, int n_ls,
                    float* __restrict__ out)
{
    float f = 0.0f;
    for (int b = threadIdx.x; b < n_blocks; b += 256)
        f += g_partials[b];

    #pragma unroll
    for (int o = 16; o > 0; o >>= 1)
        f += __shfl_xor_sync(0xffffffff, f, o);

    __shared__ float red[8];
    const int lane = threadIdx.x & 31;
    const int wid  = threadIdx.x >> 5;
    if (lane == 0) red[wid] = f;
    __syncthreads();
    if (threadIdx.x == 0) {
        float tot = 0.0f;
        #pragma unroll
        for (int w = 0; w < 8; ++w) tot += red[w];
        float s = 0.0f;
        for (int k = 0; k < n_ls; ++k) s += label_sum[k];
        out[0] = tot / s;
    }
}

extern "C" void kernel_launch(void* const* d_in, const int* in_sizes, int n_in,
                              void* d_out, int out_size)
{
    // metadata order: pred(f32), label(i32), Wl(f32[16]), label_sum(f32[16]), existmap(f32)
    const float* pred      = (const float*)d_in[0];
    const int*   label     = (const int*)  d_in[1];
    const float* Wl        = (const float*)d_in[2];
    const float* label_sum = (const float*)d_in[3];
    const float* em        = (const float*)d_in[4];
    float* out = (float*)d_out;

    const int n_total = in_sizes[0];
    const int n4 = n_total >> 2;   // 8.39M float4s (divisible by 4)

    const int threads = 256;
    int blocks = 2368;   // 4 waves x 4 CTAs/SM x 148 SMs
    int max_blocks = ((n4 >> 2) + threads - 1) / threads;
    if (blocks > max_blocks) blocks = max_blocks;
    if (blocks < 1) blocks = 1;
    if (blocks > MAX_BLOCKS) blocks = MAX_BLOCKS;

    elc_main_kernel<<<blocks, threads>>>(
        (const float4*)pred, (const int4*)label, Wl, (const float4*)em, n4);

    elc_finalize_kernel<<<1, 256>>>(label_sum, blocks, in_sizes[3], out);
}

// round 10
// speedup vs baseline: 1.0960x; 1.0960x over previous
#include <cuda_runtime.h>
#include <cuda_bf16.h>

#define EPS 0.01f

__device__ float g_acc = 0.0f;          // reset by last block each run
__device__ unsigned int g_count = 0;    // reset by last block each run

__global__ void __launch_bounds__(256, 6)   // 42-reg budget: 6 LDG.128 live
elc_fused_kernel(const float4* __restrict__ pred4,
                 const int4*   __restrict__ label4,
                 const float*  __restrict__ Wl,
                 const float*  __restrict__ label_sum,
                 const float4* __restrict__ em4,
                 int n4, int n_ls, int nblocks,
                 float* __restrict__ out)
{
    __shared__ float sWl[16];
    if (threadIdx.x < 16) sWl[threadIdx.x] = Wl[threadIdx.x];
    __syncthreads();

    float acc = 0.0f;
    const int nthreads = gridDim.x * blockDim.x;
    const int gid      = blockIdx.x * blockDim.x + threadIdx.x;
    const int npairs   = n4 >> 1;   // n4 even

    // R8's proven loop: 2 consecutive float4 per stream, 6 LDG.128
    // back-to-back -> warp presents 1KB contiguous per stream (DRAM row hits)
    for (int g = gid; g < npairs; g += nthreads) {
        const int i = g << 1;
        float4 p0 = pred4[i];
        float4 p1 = pred4[i + 1];
        int4   l0 = label4[i];
        int4   l1 = label4[i + 1];
        float4 e0 = em4[i];
        float4 e1 = em4[i + 1];

        // pair 2g,2g+1 shares one channel: c = (8g >> 18) & 15 = (g>>15)&15
        const float w = sWl[(g >> 15) & 15];

        float t = 0.0f;
        if (l0.x == 1) t += __logf(p0.x + EPS) * e0.x;
        if (l0.y == 1) t += __logf(p0.y + EPS) * e0.y;
        if (l0.z == 1) t += __logf(p0.z + EPS) * e0.z;
        if (l0.w == 1) t += __logf(p0.w + EPS) * e0.w;
        if (l1.x == 1) t += __logf(p1.x + EPS) * e1.x;
        if (l1.y == 1) t += __logf(p1.y + EPS) * e1.y;
        if (l1.z == 1) t += __logf(p1.z + EPS) * e1.z;
        if (l1.w == 1) t += __logf(p1.w + EPS) * e1.w;
        acc = fmaf(-w, t, acc);
    }

    // block reduce
    #pragma unroll
    for (int o = 16; o > 0; o >>= 1)
        acc += __shfl_xor_sync(0xffffffff, acc, o);

    __shared__ float red[8];
    const int lane = threadIdx.x & 31;
    const int wid  = threadIdx.x >> 5;
    if (lane == 0) red[wid] = acc;
    __syncthreads();
    if (wid == 0) {
        acc = (lane < (blockDim.x >> 5)) ? red[lane] : 0.0f;
        #pragma unroll
        for (int o = 4; o > 0; o >>= 1)
            acc += __shfl_xor_sync(0xffffffff, acc, o);
        if (lane == 0) atomicAdd(&g_acc, acc);   // device-scope atomic
    }
    __syncthreads();

    // arrival: ONE release-atomic per block (thread 0); RMW chain on g_count
    // makes all g_acc adds visible to the final acquirer. No per-thread fences.
    __shared__ bool s_last;
    if (threadIdx.x == 0) {
        unsigned int old;
        asm volatile("atom.acq_rel.gpu.global.add.u32 %0, [%1], %2;"
                     : "=r"(old) : "l"(&g_count), "r"(1u) : "memory");
        s_last = (old == (unsigned int)nblocks - 1u);
    }
    __syncthreads();
    if (!s_last) return;

    if (threadIdx.x == 0) {
        float tot;
        asm volatile("ld.acquire.gpu.global.f32 %0, [%1];"
                     : "=f"(tot) : "l"(&g_acc) : "memory");
        float s = 0.0f;
        for (int k = 0; k < n_ls; ++k) s += label_sum[k];
        out[0] = tot / s;
        g_acc   = 0.0f;   // reset for next graph replay (deterministic)
        g_count = 0u;
    }
}

extern "C" void kernel_launch(void* const* d_in, const int* in_sizes, int n_in,
                              void* d_out, int out_size)
{
    // metadata order: pred(f32), label(i32), Wl(f32[16]), label_sum(f32[16]), existmap(f32)
    const float* pred      = (const float*)d_in[0];
    const int*   label     = (const int*)  d_in[1];
    const float* Wl        = (const float*)d_in[2];
    const float* label_sum = (const float*)d_in[3];
    const float* em        = (const float*)d_in[4];
    float* out = (float*)d_out;

    const int n_total = in_sizes[0];
    const int n4 = n_total >> 2;   // 8.39M float4s (even)

    const int threads = 256;
    int blocks = 3552;   // 4 waves x 6 CTAs/SM x 148 SMs (R8's proven grid)
    int max_blocks = ((n4 >> 1) + threads - 1) / threads;
    if (blocks > max_blocks) blocks = max_blocks;
    if (blocks < 1) blocks = 1;

    elc_fused_kernel<<<blocks, threads>>>(
        (const float4*)pred, (const int4*)label, Wl, label_sum,
        (const float4*)em, n4, in_sizes[3], blocks, out);
}

// round 11
// speedup vs baseline: 1.1043x; 1.0076x over previous
#include <cuda_runtime.h>
#include <cuda_bf16.h>

#define EPS 0.01f

__device__ float g_acc = 0.0f;          // reset by last block each run
__device__ unsigned int g_count = 0;    // reset by last block each run

__global__ void __launch_bounds__(256, 8)   // 32 regs, 8 CTAs/SM (2048 thr/SM)
elc_fused_kernel(const float4* __restrict__ pred4,
                 const int4*   __restrict__ label4,
                 const float*  __restrict__ Wl,
                 const float*  __restrict__ label_sum,
                 const float4* __restrict__ em4,
                 int n4, int n_ls, int nblocks,
                 float* __restrict__ out)
{
    __shared__ float sWl[16];
    if (threadIdx.x < 16) sWl[threadIdx.x] = Wl[threadIdx.x];
    __syncthreads();

    float acc = 0.0f;
    const int nthreads = gridDim.x * blockDim.x;
    const int gid      = blockIdx.x * blockDim.x + threadIdx.x;
    const int npairs   = n4 >> 1;   // n4 even

    // R8/R10's proven loop: 2 consecutive float4 per stream, 6 LDG.128
    // back-to-back -> warp presents 1KB contiguous per stream (DRAM row hits)
    for (int g = gid; g < npairs; g += nthreads) {
        const int i = g << 1;
        float4 p0 = pred4[i];
        float4 p1 = pred4[i + 1];
        int4   l0 = label4[i];
        int4   l1 = label4[i + 1];
        float4 e0 = em4[i];
        float4 e1 = em4[i + 1];

        // pair 2g,2g+1 shares one channel: c = (8g >> 18) & 15 = (g>>15)&15
        const float w = sWl[(g >> 15) & 15];

        float t = 0.0f;
        if (l0.x == 1) t += __logf(p0.x + EPS) * e0.x;
        if (l0.y == 1) t += __logf(p0.y + EPS) * e0.y;
        if (l0.z == 1) t += __logf(p0.z + EPS) * e0.z;
        if (l0.w == 1) t += __logf(p0.w + EPS) * e0.w;
        if (l1.x == 1) t += __logf(p1.x + EPS) * e1.x;
        if (l1.y == 1) t += __logf(p1.y + EPS) * e1.y;
        if (l1.z == 1) t += __logf(p1.z + EPS) * e1.z;
        if (l1.w == 1) t += __logf(p1.w + EPS) * e1.w;
        acc = fmaf(-w, t, acc);
    }

    // block reduce
    #pragma unroll
    for (int o = 16; o > 0; o >>= 1)
        acc += __shfl_xor_sync(0xffffffff, acc, o);

    __shared__ float red[8];
    const int lane = threadIdx.x & 31;
    const int wid  = threadIdx.x >> 5;
    if (lane == 0) red[wid] = acc;
    __syncthreads();
    if (wid == 0) {
        acc = (lane < (blockDim.x >> 5)) ? red[lane] : 0.0f;
        #pragma unroll
        for (int o = 4; o > 0; o >>= 1)
            acc += __shfl_xor_sync(0xffffffff, acc, o);
        if (lane == 0) atomicAdd(&g_acc, acc);   // device-scope atomic
    }
    __syncthreads();

    // arrival: ONE release-atomic per block (thread 0); RMW chain on g_count
    // makes all g_acc adds visible to the final acquirer. No per-thread fences.
    __shared__ bool s_last;
    if (threadIdx.x == 0) {
        unsigned int old;
        asm volatile("atom.acq_rel.gpu.global.add.u32 %0, [%1], %2;"
                     : "=r"(old) : "l"(&g_count), "r"(1u) : "memory");
        s_last = (old == (unsigned int)nblocks - 1u);
    }
    __syncthreads();
    if (!s_last) return;

    if (threadIdx.x == 0) {
        float tot;
        asm volatile("ld.acquire.gpu.global.f32 %0, [%1];"
                     : "=f"(tot) : "l"(&g_acc) : "memory");
        float s = 0.0f;
        for (int k = 0; k < n_ls; ++k) s += label_sum[k];
        out[0] = tot / s;
        g_acc   = 0.0f;   // reset for next graph replay (deterministic)
        g_count = 0u;
    }
}

extern "C" void kernel_launch(void* const* d_in, const int* in_sizes, int n_in,
                              void* d_out, int out_size)
{
    // metadata order: pred(f32), label(i32), Wl(f32[16]), label_sum(f32[16]), existmap(f32)
    const float* pred      = (const float*)d_in[0];
    const int*   label     = (const int*)  d_in[1];
    const float* Wl        = (const float*)d_in[2];
    const float* label_sum = (const float*)d_in[3];
    const float* em        = (const float*)d_in[4];
    float* out = (float*)d_out;

    const int n_total = in_sizes[0];
    const int n4 = n_total >> 2;   // 8.39M float4s (even)

    const int threads = 256;
    int blocks = 4736;   // 4 waves x 8 CTAs/SM x 148 SMs
    int max_blocks = ((n4 >> 1) + threads - 1) / threads;
    if (blocks > max_blocks) blocks = max_blocks;
    if (blocks < 1) blocks = 1;

    elc_fused_kernel<<<blocks, threads>>>(
        (const float4*)pred, (const int4*)label, Wl, label_sum,
        (const float4*)em, n4, in_sizes[3], blocks, out);
}